// round 4
// baseline (speedup 1.0000x reference)
#include <cuda_runtime.h>
#include <cstdint>

#define NN 100000
#define NE 800000
#define H  64
#define NT 256
#define XP 68                  // proj x smem pitch (floats)
#define UP 132                 // upd in smem pitch (floats)
#define SMEM_PROJ ((8192 + 64 + 64 * XP) * 4)
#define SMEM_UPD  ((8192 + 192 + 128 * UP) * 4)
#define NBLK 391               // scan blocks (391*256 >= NN)

// Scratch (device globals: allocation-free rule)
__device__ __align__(16) float g_x[(size_t)NN * H];
__device__ __align__(16) float g_p1[(size_t)NN * H];
__device__ __align__(16) float g_p2[(size_t)NN * H];
__device__ __align__(16) float g_agg[(size_t)NN * H];
__device__ int g_deg[NN];
__device__ int g_off[NN + 1];
__device__ int g_cur[NN];
__device__ int g_csr[NE];
__device__ int g_bsum[NBLK];
__device__ int g_boff[NBLK];
__device__ float g_sum[H];
__device__ unsigned g_maxb[H];

// ---------- packed f32x2 helpers ----------
__device__ __forceinline__ uint64_t pk2(float lo, float hi) {
    uint64_t r;
    asm("mov.b64 %0, {%1, %2};" : "=l"(r) : "r"(__float_as_uint(lo)), "r"(__float_as_uint(hi)));
    return r;
}
__device__ __forceinline__ uint64_t dup2(float a) {
    uint64_t r;
    asm("mov.b64 %0, {%1, %1};" : "=l"(r) : "r"(__float_as_uint(a)));
    return r;
}
__device__ __forceinline__ void fma2(uint64_t& acc, uint64_t w, uint64_t p) {
    asm("fma.rn.f32x2 %0, %1, %2, %0;" : "+l"(acc) : "l"(w), "l"(p));
}
__device__ __forceinline__ void unpk(uint64_t v, float& lo, float& hi) {
    unsigned a, b;
    asm("mov.b64 {%0, %1}, %2;" : "=r"(a), "=r"(b) : "l"(v));
    lo = __uint_as_float(a); hi = __uint_as_float(b);
}
__device__ __forceinline__ unsigned encf(float f) {
    unsigned u = __float_as_uint(f);
    return (u & 0x80000000u) ? ~u : (u | 0x80000000u);
}
__device__ __forceinline__ float decf(unsigned u) {
    return (u & 0x80000000u) ? __uint_as_float(u & 0x7FFFFFFFu) : __uint_as_float(~u);
}

// ---------- setup ----------
__global__ void k_embed(const int* __restrict__ ti, const float* __restrict__ et) {
    int i = blockIdx.x * blockDim.x + threadIdx.x;
    int stride = gridDim.x * blockDim.x;
    for (int lin = i; lin < NN * 16; lin += stride) {
        int n = lin >> 4, q = lin & 15;
        ((float4*)g_x)[lin] = ((const float4*)et)[ti[n] * 16 + q];
    }
    for (int n = i; n < NN; n += stride) g_deg[n] = 0;
    if (i < H) { g_sum[i] = 0.f; g_maxb[i] = 0u; }
}

__global__ void k_hist(const int* __restrict__ edges) {
    int i = blockIdx.x * blockDim.x + threadIdx.x;
    int stride = gridDim.x * blockDim.x;
    for (int e = i; e < NE; e += stride)
        atomicAdd(&g_deg[((const int2*)edges)[e].y], 1);
}

// ---------- exclusive scan of g_deg -> g_off ----------
__global__ void k_scan1() {
    __shared__ int s[256];
    int t = threadIdx.x;
    int i = blockIdx.x * 256 + t;
    int v = (i < NN) ? g_deg[i] : 0;
    s[t] = v;
    __syncthreads();
    #pragma unroll
    for (int d = 1; d < 256; d <<= 1) {
        int tv = (t >= d) ? s[t - d] : 0;
        __syncthreads();
        s[t] += tv;
        __syncthreads();
    }
    if (i < NN) g_off[i] = s[t] - v;
    if (t == 255) g_bsum[blockIdx.x] = s[255];
}

__global__ void k_scan2() {
    __shared__ int s[512];
    int t = threadIdx.x;
    int v = (t < NBLK) ? g_bsum[t] : 0;
    s[t] = v;
    __syncthreads();
    #pragma unroll
    for (int d = 1; d < 512; d <<= 1) {
        int tv = (t >= d) ? s[t - d] : 0;
        __syncthreads();
        s[t] += tv;
        __syncthreads();
    }
    if (t < NBLK) g_boff[t] = s[t] - v;
}

__global__ void k_scan3() {
    int i = blockIdx.x * blockDim.x + threadIdx.x;
    if (i < NN) {
        int val = g_off[i] + g_boff[i >> 8];
        g_off[i] = val;
        g_cur[i] = val;
    }
    if (i == 0) g_off[NN] = NE;
}

__global__ void k_scatter(const int* __restrict__ edges) {
    int e = blockIdx.x * blockDim.x + threadIdx.x;
    if (e < NE) {
        int2 ed = ((const int2*)edges)[e];
        int pos = atomicAdd(&g_cur[ed.y], 1);
        g_csr[pos] = ed.x;
    }
}

// ---------- per-node projection: P1 = x@W[:64]; P2 = x@W[64:] + b ----------
// thread: 2 rows (rg, rg+32) x (8 P1 cols + 8 P2 cols)
__global__ __launch_bounds__(NT, 3) void k_proj(const float* __restrict__ W,
                                                const float* __restrict__ B) {
    extern __shared__ float sm[];
    float* Wsh = sm;              // 8192 (W: [128][64])
    float* bsh = sm + 8192;       // 64
    float* xsh = sm + 8256;       // 64 * XP

    const int tid = threadIdx.x;
    for (int i = tid; i < 2048; i += NT) ((float4*)Wsh)[i] = ((const float4*)W)[i];
    if (tid < 16) ((float4*)bsh)[tid] = ((const float4*)B)[tid];
    __syncthreads();

    const int cg = tid & 7, rg = tid >> 3;   // rg 0..31
    const int c0 = cg * 8;

    const int ntiles = (NN + 63) / 64;
    for (int tile = blockIdx.x; tile < ntiles; tile += gridDim.x) {
        const int base = tile * 64;
        #pragma unroll
        for (int r = 0; r < 4; r++) {
            int lin = r * NT + tid;
            int nl = lin >> 4, q = lin & 15;
            int gn = base + nl;
            float4 v = make_float4(0.f, 0.f, 0.f, 0.f);
            if (gn < NN) v = ((const float4*)g_x)[gn * 16 + q];
            ((float4*)(xsh + nl * XP))[q] = v;
        }
        __syncthreads();

        uint64_t a1[2][4], a2[2][4];
        {
            uint64_t b0 = pk2(bsh[c0+0], bsh[c0+1]);
            uint64_t b1 = pk2(bsh[c0+2], bsh[c0+3]);
            uint64_t b2 = pk2(bsh[c0+4], bsh[c0+5]);
            uint64_t b3 = pk2(bsh[c0+6], bsh[c0+7]);
            #pragma unroll
            for (int j = 0; j < 2; j++) {
                a1[j][0] = 0;  a1[j][1] = 0;  a1[j][2] = 0;  a1[j][3] = 0;
                a2[j][0] = b0; a2[j][1] = b1; a2[j][2] = b2; a2[j][3] = b3;
            }
        }

        #pragma unroll 4
        for (int k0 = 0; k0 < 64; k0 += 4) {
            float xr[2][4];
            #pragma unroll
            for (int j = 0; j < 2; j++) {
                float4 t = *(const float4*)(xsh + (rg + 32 * j) * XP + k0);
                xr[j][0] = t.x; xr[j][1] = t.y; xr[j][2] = t.z; xr[j][3] = t.w;
            }
            #pragma unroll
            for (int i = 0; i < 4; i++) {
                ulonglong2 wa = *(const ulonglong2*)(Wsh + (k0 + i) * 64 + c0);
                ulonglong2 wb = *(const ulonglong2*)(Wsh + (k0 + i) * 64 + c0 + 4);
                ulonglong2 wc = *(const ulonglong2*)(Wsh + (64 + k0 + i) * 64 + c0);
                ulonglong2 wd = *(const ulonglong2*)(Wsh + (64 + k0 + i) * 64 + c0 + 4);
                #pragma unroll
                for (int j = 0; j < 2; j++) {
                    uint64_t p = dup2(xr[j][i]);
                    fma2(a1[j][0], wa.x, p); fma2(a1[j][1], wa.y, p);
                    fma2(a1[j][2], wb.x, p); fma2(a1[j][3], wb.y, p);
                    fma2(a2[j][0], wc.x, p); fma2(a2[j][1], wc.y, p);
                    fma2(a2[j][2], wd.x, p); fma2(a2[j][3], wd.y, p);
                }
            }
        }

        #pragma unroll
        for (int j = 0; j < 2; j++) {
            int gn = base + rg + 32 * j;
            if (gn < NN) {
                float v0, v1, v2, v3, v4, v5, v6, v7;
                unpk(a1[j][0], v0, v1); unpk(a1[j][1], v2, v3);
                unpk(a1[j][2], v4, v5); unpk(a1[j][3], v6, v7);
                float4* d1 = (float4*)(g_p1 + (size_t)gn * H + c0);
                d1[0] = make_float4(v0, v1, v2, v3);
                d1[1] = make_float4(v4, v5, v6, v7);
                unpk(a2[j][0], v0, v1); unpk(a2[j][1], v2, v3);
                unpk(a2[j][2], v4, v5); unpk(a2[j][3], v6, v7);
                float4* d2 = (float4*)(g_p2 + (size_t)gn * H + c0);
                d2[0] = make_float4(v0, v1, v2, v3);
                d2[1] = make_float4(v4, v5, v6, v7);
            }
        }
        __syncthreads();
    }
}

// ---------- CSR edge pass: agg[n] = sum_{src in N(n)} relu(P1[src] + P2[n]) ----------
__global__ __launch_bounds__(NT) void k_edge() {
    int idx = blockIdx.x * NT + threadIdx.x;  // NN*8 tasks exactly
    int n = idx >> 3, q = idx & 7;
    int s0 = g_off[n], s1 = g_off[n + 1];
    const float4* p2 = (const float4*)(g_p2 + (size_t)n * H) + q * 2;
    float4 b0 = p2[0], b1 = p2[1];
    float a[8] = {0.f, 0.f, 0.f, 0.f, 0.f, 0.f, 0.f, 0.f};
    for (int i = s0; i < s1; i++) {
        int src = g_csr[i];
        const float4* p1 = (const float4*)(g_p1 + (size_t)src * H) + q * 2;
        float4 c0 = p1[0], c1 = p1[1];
        a[0] += fmaxf(c0.x + b0.x, 0.f); a[1] += fmaxf(c0.y + b0.y, 0.f);
        a[2] += fmaxf(c0.z + b0.z, 0.f); a[3] += fmaxf(c0.w + b0.w, 0.f);
        a[4] += fmaxf(c1.x + b1.x, 0.f); a[5] += fmaxf(c1.y + b1.y, 0.f);
        a[6] += fmaxf(c1.z + b1.z, 0.f); a[7] += fmaxf(c1.w + b1.w, 0.f);
    }
    float4* dst = (float4*)(g_agg + (size_t)n * H + q * 8);
    dst[0] = make_float4(a[0], a[1], a[2], a[3]);
    dst[1] = make_float4(a[4], a[5], a[6], a[7]);
}

// ---------- node update GEMM + residual + LayerNorm ----------
// thread: 4 rows (rg + 32j) x 8 cols, TR=128
__global__ __launch_bounds__(NT, 2) void k_upd(const float* __restrict__ W,
                                               const float* __restrict__ B,
                                               const float* __restrict__ lng,
                                               const float* __restrict__ lnb) {
    extern __shared__ float sm[];
    float* Wsh  = sm;            // 8192  (W: [128][64])
    float* bsh  = sm + 8192;     // 64
    float* gsh  = sm + 8256;     // 64
    float* b2sh = sm + 8320;     // 64
    float* insh = sm + 8384;     // 128 * UP

    const int tid = threadIdx.x;
    for (int i = tid; i < 2048; i += NT) ((float4*)Wsh)[i] = ((const float4*)W)[i];
    if (tid < 16) ((float4*)bsh)[tid] = ((const float4*)B)[tid];
    else if (tid < 32) ((float4*)gsh)[tid - 16]  = ((const float4*)lng)[tid - 16];
    else if (tid < 48) ((float4*)b2sh)[tid - 32] = ((const float4*)lnb)[tid - 32];
    __syncthreads();

    const int cg = tid & 7, rg = tid >> 3;   // rg 0..31
    const int c0 = cg * 8;

    const int ntiles = (NN + 127) / 128;
    for (int tile = blockIdx.x; tile < ntiles; tile += gridDim.x) {
        const int base = tile * 128;
        #pragma unroll
        for (int r = 0; r < 16; r++) {
            int lin = r * NT + tid;
            int nl = lin >> 5, q = lin & 31;
            int gn = base + nl;
            float4 v = make_float4(0.f, 0.f, 0.f, 0.f);
            if (gn < NN) {
                if (q < 16) {
                    v = ((const float4*)g_x)[gn * 16 + q];
                } else {
                    v = ((const float4*)g_agg)[gn * 16 + (q - 16)];
                    float ic = 1.0f / fmaxf((float)g_deg[gn], 1.0f);
                    v.x *= ic; v.y *= ic; v.z *= ic; v.w *= ic;
                }
            }
            ((float4*)(insh + nl * UP))[q] = v;
        }
        __syncthreads();

        uint64_t acc[4][4];
        {
            uint64_t b0 = pk2(bsh[c0+0], bsh[c0+1]);
            uint64_t b1 = pk2(bsh[c0+2], bsh[c0+3]);
            uint64_t b2 = pk2(bsh[c0+4], bsh[c0+5]);
            uint64_t b3 = pk2(bsh[c0+6], bsh[c0+7]);
            #pragma unroll
            for (int j = 0; j < 4; j++) {
                acc[j][0] = b0; acc[j][1] = b1; acc[j][2] = b2; acc[j][3] = b3;
            }
        }

        #pragma unroll 4
        for (int k0 = 0; k0 < 128; k0 += 4) {
            float xr[4][4];
            #pragma unroll
            for (int j = 0; j < 4; j++) {
                float4 t = *(const float4*)(insh + (rg + 32 * j) * UP + k0);
                xr[j][0] = t.x; xr[j][1] = t.y; xr[j][2] = t.z; xr[j][3] = t.w;
            }
            #pragma unroll
            for (int i = 0; i < 4; i++) {
                ulonglong2 wa = *(const ulonglong2*)(Wsh + (k0 + i) * 64 + c0);
                ulonglong2 wb = *(const ulonglong2*)(Wsh + (k0 + i) * 64 + c0 + 4);
                #pragma unroll
                for (int j = 0; j < 4; j++) {
                    uint64_t p = dup2(xr[j][i]);
                    fma2(acc[j][0], wa.x, p); fma2(acc[j][1], wa.y, p);
                    fma2(acc[j][2], wb.x, p); fma2(acc[j][3], wb.y, p);
                }
            }
        }

        // epilogue: relu + residual + LN (8-lane groups own a row)
        #pragma unroll
        for (int j = 0; j < 4; j++) {
            int row = rg + 32 * j;
            int gn = base + row;
            float h[8];
            {
                float u0, u1;
                unpk(acc[j][0], u0, u1); h[0] = fmaxf(u0, 0.f); h[1] = fmaxf(u1, 0.f);
                unpk(acc[j][1], u0, u1); h[2] = fmaxf(u0, 0.f); h[3] = fmaxf(u1, 0.f);
                unpk(acc[j][2], u0, u1); h[4] = fmaxf(u0, 0.f); h[5] = fmaxf(u1, 0.f);
                unpk(acc[j][3], u0, u1); h[6] = fmaxf(u0, 0.f); h[7] = fmaxf(u1, 0.f);
            }
            const float* xo = insh + row * UP + c0;
            float s1 = 0.f, s2 = 0.f;
            #pragma unroll
            for (int i = 0; i < 8; i++) {
                h[i] += xo[i];
                s1 += h[i]; s2 += h[i] * h[i];
            }
            #pragma unroll
            for (int d = 1; d < 8; d <<= 1) {
                s1 += __shfl_xor_sync(0xFFFFFFFFu, s1, d);
                s2 += __shfl_xor_sync(0xFFFFFFFFu, s2, d);
            }
            float mu  = s1 * 0.015625f;
            float var = s2 * 0.015625f - mu * mu;
            float sc  = rsqrtf(fmaxf(var, 0.f) + 1e-5f);
            if (gn < NN) {
                float o[8];
                #pragma unroll
                for (int i = 0; i < 8; i++)
                    o[i] = (h[i] - mu) * sc * gsh[c0 + i] + b2sh[c0 + i];
                float4* dst = (float4*)(g_x + (size_t)gn * H + c0);
                dst[0] = make_float4(o[0], o[1], o[2], o[3]);
                dst[1] = make_float4(o[4], o[5], o[6], o[7]);
            }
        }
        __syncthreads();
    }
}

// ---------- final mean/max over nodes ----------
__global__ void k_reduce() {
    __shared__ float rs[4][64];
    __shared__ float rm[4][64];
    int j = threadIdx.x & 63, g = threadIdx.x >> 6;
    float s = 0.f, m = -3.402823466e38f;
    for (int n = blockIdx.x * 4 + g; n < NN; n += gridDim.x * 4) {
        float v = g_x[(size_t)n * H + j];
        s += v; m = fmaxf(m, v);
    }
    rs[g][j] = s; rm[g][j] = m;
    __syncthreads();
    if (g == 0) {
        #pragma unroll
        for (int i = 1; i < 4; i++) { s += rs[i][j]; m = fmaxf(m, rm[i][j]); }
        atomicAdd(&g_sum[j], s);
        atomicMax(&g_maxb[j], encf(m));
    }
}

__global__ void k_final(float* out) {
    int t = threadIdx.x;
    if (t < 64) out[t] = g_sum[t] * (1.0f / NN);
    else        out[t] = decf(g_maxb[t - 64]);
}

// ---------- launch ----------
extern "C" void kernel_launch(void* const* d_in, const int* in_sizes, int n_in,
                              void* d_out, int out_size) {
    const int*   ti    = (const int*)d_in[0];
    const int*   edges = (const int*)d_in[1];
    const float* et    = (const float*)d_in[2];
    const float* msg_w = (const float*)d_in[3];
    const float* msg_b = (const float*)d_in[4];
    const float* upd_w = (const float*)d_in[5];
    const float* upd_b = (const float*)d_in[6];
    const float* lng   = (const float*)d_in[7];
    const float* lnb   = (const float*)d_in[8];
    float* out = (float*)d_out;

    cudaFuncSetAttribute(k_proj, cudaFuncAttributeMaxDynamicSharedMemorySize, SMEM_PROJ);
    cudaFuncSetAttribute(k_upd,  cudaFuncAttributeMaxDynamicSharedMemorySize, SMEM_UPD);

    k_embed<<<512, 256>>>(ti, et);
    k_hist<<<512, 256>>>(edges);
    k_scan1<<<NBLK, 256>>>();
    // layer-0 proj placed 4th so ncu (-s5 -c1) profiles it
    k_proj<<<444, NT, SMEM_PROJ>>>(msg_w, msg_b);
    k_scan2<<<1, 512>>>();
    k_scan3<<<392, 256>>>();
    k_scatter<<<(NE + 255) / 256, 256>>>(edges);

    for (int l = 0; l < 3; l++) {
        if (l > 0) k_proj<<<444, NT, SMEM_PROJ>>>(msg_w + l * 8192, msg_b + l * 64);
        k_edge<<<NN * 8 / NT, NT>>>();
        k_upd<<<296, NT, SMEM_UPD>>>(upd_w + l * 8192, upd_b + l * 64,
                                     lng + l * 64, lnb + l * 64);
    }

    k_reduce<<<296, 256>>>();
    k_final<<<1, 128>>>(out);
}

// round 5
// speedup vs baseline: 1.5436x; 1.5436x over previous
#include <cuda_runtime.h>
#include <cstdint>

#define NN 100000
#define NE 800000
#define H  64
#define NT 256
#define XP 68                  // proj x smem pitch (floats)
#define UP 132                 // upd in smem pitch (floats)
#define SMEM_PROJ ((8192 + 64 * XP) * 4)
#define SMEM_UPD  ((8192 + 192 + 64 * UP) * 4)
#define NBLK 391               // scan blocks (391*256 >= NN)

// Scratch (device globals: allocation-free rule)
__device__ __align__(16) float g_x[(size_t)NN * H];
__device__ __align__(16) float g_p1[(size_t)NN * H];
__device__ __align__(16) float g_p2[(size_t)NN * H];
__device__ __align__(16) float g_agg[(size_t)NN * H];
__device__ __align__(16) float g_wpp[3 * 8192];   // proj weights, pair-packed
__device__ __align__(16) float g_wpu[3 * 8192];   // upd weights, pair-packed
__device__ int g_deg[NN];
__device__ int g_off[NN + 1];
__device__ int g_cur[NN];
__device__ int g_csr[NE];
__device__ int g_bsum[NBLK];
__device__ int g_boff[NBLK];
__device__ float g_sum[H];
__device__ unsigned g_maxb[H];

// ---------- packed f32x2 helpers ----------
__device__ __forceinline__ uint64_t pk2(float lo, float hi) {
    uint64_t r;
    asm("mov.b64 %0, {%1, %2};" : "=l"(r) : "r"(__float_as_uint(lo)), "r"(__float_as_uint(hi)));
    return r;
}
__device__ __forceinline__ void fma2(uint64_t& acc, uint64_t w, uint64_t p) {
    asm("fma.rn.f32x2 %0, %1, %2, %0;" : "+l"(acc) : "l"(w), "l"(p));
}
__device__ __forceinline__ float unpk_sum(uint64_t v) {
    unsigned a, b;
    asm("mov.b64 {%0, %1}, %2;" : "=r"(a), "=r"(b) : "l"(v));
    return __uint_as_float(a) + __uint_as_float(b);
}
__device__ __forceinline__ unsigned encf(float f) {
    unsigned u = __float_as_uint(f);
    return (u & 0x80000000u) ? ~u : (u | 0x80000000u);
}
__device__ __forceinline__ float decf(unsigned u) {
    return (u & 0x80000000u) ? __uint_as_float(u & 0x7FFFFFFFu) : __uint_as_float(~u);
}

// ---------- setup ----------
__global__ void k_embed(const int* __restrict__ ti, const float* __restrict__ et) {
    int i = blockIdx.x * blockDim.x + threadIdx.x;
    int stride = gridDim.x * blockDim.x;
    for (int lin = i; lin < NN * 16; lin += stride) {
        int n = lin >> 4, q = lin & 15;
        ((float4*)g_x)[lin] = ((const float4*)et)[ti[n] * 16 + q];
    }
    for (int n = i; n < NN; n += stride) g_deg[n] = 0;
    if (i < H) { g_sum[i] = 0.f; g_maxb[i] = 0u; }
}

__global__ void k_hist(const int* __restrict__ edges) {
    int i = blockIdx.x * blockDim.x + threadIdx.x;
    int stride = gridDim.x * blockDim.x;
    for (int e = i; e < NE; e += stride)
        atomicAdd(&g_deg[((const int2*)edges)[e].y], 1);
}

// ---------- weight prepack: pair-major (k-pair packed) layouts ----------
// proj: g_wpp[l][ (t*128 + C)*2 + s ] = msg_w[l][ (C<64 ? 2t+s : 64+2t+s) ][ C&63 ],  t in 0..31
// upd:  g_wpu[l][ (t*64  + c)*2 + s ] = upd_w[l][ 2t+s ][ c ],                        t in 0..63
__global__ void k_prepack(const float* __restrict__ msg_w, const float* __restrict__ upd_w) {
    int i = blockIdx.x * blockDim.x + threadIdx.x;
    int stride = gridDim.x * blockDim.x;
    for (int idx = i; idx < 3 * 8192; idx += stride) {
        int l = idx / 8192, r = idx % 8192;
        int s = r & 1, tC = r >> 1;
        int C = tC & 127, t = tC >> 7;
        int row = (C < 64) ? (2 * t + s) : (64 + 2 * t + s);
        g_wpp[idx] = msg_w[l * 8192 + row * 64 + (C & 63)];
    }
    for (int idx = i; idx < 3 * 8192; idx += stride) {
        int l = idx / 8192, r = idx % 8192;
        int s = r & 1, tc = r >> 1;
        int c = tc & 63, t = tc >> 6;
        g_wpu[idx] = upd_w[l * 8192 + (2 * t + s) * 64 + c];
    }
}

// ---------- exclusive scan of g_deg -> g_off ----------
__global__ void k_scan1() {
    __shared__ int s[256];
    int t = threadIdx.x;
    int i = blockIdx.x * 256 + t;
    int v = (i < NN) ? g_deg[i] : 0;
    s[t] = v;
    __syncthreads();
    #pragma unroll
    for (int d = 1; d < 256; d <<= 1) {
        int tv = (t >= d) ? s[t - d] : 0;
        __syncthreads();
        s[t] += tv;
        __syncthreads();
    }
    if (i < NN) g_off[i] = s[t] - v;
    if (t == 255) g_bsum[blockIdx.x] = s[255];
}

__global__ void k_scan2() {
    __shared__ int s[512];
    int t = threadIdx.x;
    int v = (t < NBLK) ? g_bsum[t] : 0;
    s[t] = v;
    __syncthreads();
    #pragma unroll
    for (int d = 1; d < 512; d <<= 1) {
        int tv = (t >= d) ? s[t - d] : 0;
        __syncthreads();
        s[t] += tv;
        __syncthreads();
    }
    if (t < NBLK) g_boff[t] = s[t] - v;
}

__global__ void k_scan3() {
    int i = blockIdx.x * blockDim.x + threadIdx.x;
    if (i < NN) {
        int val = g_off[i] + g_boff[i >> 8];
        g_off[i] = val;
        g_cur[i] = val;
    }
    if (i == 0) g_off[NN] = NE;
}

__global__ void k_scatter(const int* __restrict__ edges) {
    int e = blockIdx.x * blockDim.x + threadIdx.x;
    if (e < NE) {
        int2 ed = ((const int2*)edges)[e];
        int pos = atomicAdd(&g_cur[ed.y], 1);
        g_csr[pos] = ed.x;
    }
}

// ---------- per-node projection: P1 = x@W[:64]; P2 = x@W[64:] + b ----------
// k-pair packed. thread: 8 rows (rg + 8j) x (2 P1 cols + 2 P2 cols), TR=64.
__global__ __launch_bounds__(NT, 2) void k_proj(const float* __restrict__ Wp,
                                                const float* __restrict__ B) {
    extern __shared__ float sm[];
    float* Wsh = sm;              // 8192 pair-packed: (t*128 + C)*2 + s
    float* xsh = sm + 8192;       // 64 * XP

    const int tid = threadIdx.x;
    for (int i = tid; i < 2048; i += NT) ((float4*)Wsh)[i] = ((const float4*)Wp)[i];
    __syncthreads();

    const int cg = tid & 31, rg = tid >> 5;   // rg = warp id 0..7
    const int c2 = cg * 2;                    // cols c2, c2+1 in each of P1/P2
    const float bias0 = B[c2], bias1 = B[c2 + 1];

    const int ntiles = (NN + 63) / 64;
    for (int tile = blockIdx.x; tile < ntiles; tile += gridDim.x) {
        const int base = tile * 64;
        #pragma unroll
        for (int r = 0; r < 4; r++) {
            int lin = r * NT + tid;
            int nl = lin >> 4, q = lin & 15;
            int gn = base + nl;
            float4 v = make_float4(0.f, 0.f, 0.f, 0.f);
            if (gn < NN) v = ((const float4*)g_x)[gn * 16 + q];
            ((float4*)(xsh + nl * XP))[q] = v;
        }
        __syncthreads();

        uint64_t acc[8][4];
        {
            uint64_t zb0 = pk2(bias0, 0.f), zb1 = pk2(bias1, 0.f);
            #pragma unroll
            for (int j = 0; j < 8; j++) {
                acc[j][0] = 0;   acc[j][1] = 0;     // P1
                acc[j][2] = zb0; acc[j][3] = zb1;   // P2 (+bias)
            }
        }

        // k loop: t2 covers 4 k's (2 k-pairs)
        #pragma unroll 2
        for (int t2 = 0; t2 < 16; t2++) {
            ulonglong2 xv[8];
            #pragma unroll
            for (int j = 0; j < 8; j++)
                xv[j] = *(const ulonglong2*)(xsh + (rg + 8 * j) * XP + 4 * t2);
            #pragma unroll
            for (int p = 0; p < 2; p++) {
                int t = 2 * t2 + p;
                ulonglong2 w1 = *(const ulonglong2*)(Wsh + (t * 128 + c2) * 2);
                ulonglong2 w2 = *(const ulonglong2*)(Wsh + (t * 128 + 64 + c2) * 2);
                #pragma unroll
                for (int j = 0; j < 8; j++) {
                    uint64_t x2 = p ? xv[j].y : xv[j].x;
                    fma2(acc[j][0], w1.x, x2); fma2(acc[j][1], w1.y, x2);
                    fma2(acc[j][2], w2.x, x2); fma2(acc[j][3], w2.y, x2);
                }
            }
        }

        #pragma unroll
        for (int j = 0; j < 8; j++) {
            int gn = base + rg + 8 * j;
            if (gn < NN) {
                *(float2*)(g_p1 + (size_t)gn * H + c2) =
                    make_float2(unpk_sum(acc[j][0]), unpk_sum(acc[j][1]));
                *(float2*)(g_p2 + (size_t)gn * H + c2) =
                    make_float2(unpk_sum(acc[j][2]), unpk_sum(acc[j][3]));
            }
        }
        __syncthreads();
    }
}

// ---------- CSR edge pass: agg[n] = sum_{src in N(n)} relu(P1[src] + P2[n]) ----------
__global__ __launch_bounds__(NT) void k_edge() {
    int idx = blockIdx.x * NT + threadIdx.x;  // NN*8 tasks exactly
    int n = idx >> 3, q = idx & 7;
    int s0 = g_off[n], s1 = g_off[n + 1];
    const float4* p2 = (const float4*)(g_p2 + (size_t)n * H) + q * 2;
    float4 b0 = p2[0], b1 = p2[1];
    float a[8] = {0.f, 0.f, 0.f, 0.f, 0.f, 0.f, 0.f, 0.f};
    for (int i = s0; i < s1; i++) {
        int src = g_csr[i];
        const float4* p1 = (const float4*)(g_p1 + (size_t)src * H) + q * 2;
        float4 c0 = p1[0], c1 = p1[1];
        a[0] += fmaxf(c0.x + b0.x, 0.f); a[1] += fmaxf(c0.y + b0.y, 0.f);
        a[2] += fmaxf(c0.z + b0.z, 0.f); a[3] += fmaxf(c0.w + b0.w, 0.f);
        a[4] += fmaxf(c1.x + b1.x, 0.f); a[5] += fmaxf(c1.y + b1.y, 0.f);
        a[6] += fmaxf(c1.z + b1.z, 0.f); a[7] += fmaxf(c1.w + b1.w, 0.f);
    }
    float4* dst = (float4*)(g_agg + (size_t)n * H + q * 8);
    dst[0] = make_float4(a[0], a[1], a[2], a[3]);
    dst[1] = make_float4(a[4], a[5], a[6], a[7]);
}

// ---------- node update GEMM + residual + LayerNorm ----------
// k-pair packed. thread: 4 rows (rg + 16j) x 4 cols {c2,c2+1,32+c2,33+c2}, TR=64.
__global__ __launch_bounds__(NT, 3) void k_upd(const float* __restrict__ Wp,
                                               const float* __restrict__ B,
                                               const float* __restrict__ lng,
                                               const float* __restrict__ lnb) {
    extern __shared__ float sm[];
    float* Wsh  = sm;            // 8192 pair-packed: (t*64 + c)*2 + s
    float* bsh  = sm + 8192;     // 64
    float* gsh  = sm + 8256;     // 64
    float* b2sh = sm + 8320;     // 64
    float* insh = sm + 8384;     // 64 * UP

    const int tid = threadIdx.x;
    for (int i = tid; i < 2048; i += NT) ((float4*)Wsh)[i] = ((const float4*)Wp)[i];
    if (tid < 16) ((float4*)bsh)[tid] = ((const float4*)B)[tid];
    else if (tid < 32) ((float4*)gsh)[tid - 16]  = ((const float4*)lng)[tid - 16];
    else if (tid < 48) ((float4*)b2sh)[tid - 32] = ((const float4*)lnb)[tid - 32];
    __syncthreads();

    const int cg = tid & 15, rg = tid >> 4;   // rg 0..15
    const int c2 = cg * 2;                    // cols c2,c2+1 and 32+c2,33+c2

    const int ntiles = (NN + 63) / 64;
    for (int tile = blockIdx.x; tile < ntiles; tile += gridDim.x) {
        const int base = tile * 64;
        #pragma unroll
        for (int r = 0; r < 8; r++) {
            int lin = r * NT + tid;
            int nl = lin >> 5, q = lin & 31;
            int gn = base + nl;
            float4 v = make_float4(0.f, 0.f, 0.f, 0.f);
            if (gn < NN) {
                if (q < 16) {
                    v = ((const float4*)g_x)[gn * 16 + q];
                } else {
                    v = ((const float4*)g_agg)[gn * 16 + (q - 16)];
                    float ic = 1.0f / fmaxf((float)g_deg[gn], 1.0f);
                    v.x *= ic; v.y *= ic; v.z *= ic; v.w *= ic;
                }
            }
            ((float4*)(insh + nl * UP))[q] = v;
        }
        __syncthreads();

        uint64_t acc[4][4];
        {
            uint64_t b0 = pk2(bsh[c2], 0.f),      b1 = pk2(bsh[c2 + 1], 0.f);
            uint64_t b2 = pk2(bsh[32 + c2], 0.f), b3 = pk2(bsh[33 + c2], 0.f);
            #pragma unroll
            for (int j = 0; j < 4; j++) {
                acc[j][0] = b0; acc[j][1] = b1; acc[j][2] = b2; acc[j][3] = b3;
            }
        }

        #pragma unroll 4
        for (int t2 = 0; t2 < 32; t2++) {
            ulonglong2 xv[4];
            #pragma unroll
            for (int j = 0; j < 4; j++)
                xv[j] = *(const ulonglong2*)(insh + (rg + 16 * j) * UP + 4 * t2);
            #pragma unroll
            for (int p = 0; p < 2; p++) {
                int t = 2 * t2 + p;
                ulonglong2 w1 = *(const ulonglong2*)(Wsh + (t * 64 + c2) * 2);
                ulonglong2 w2 = *(const ulonglong2*)(Wsh + (t * 64 + 32 + c2) * 2);
                #pragma unroll
                for (int j = 0; j < 4; j++) {
                    uint64_t x2 = p ? xv[j].y : xv[j].x;
                    fma2(acc[j][0], w1.x, x2); fma2(acc[j][1], w1.y, x2);
                    fma2(acc[j][2], w2.x, x2); fma2(acc[j][3], w2.y, x2);
                }
            }
        }

        // epilogue: relu + residual + LN (16-lane groups own a row)
        #pragma unroll
        for (int j = 0; j < 4; j++) {
            int row = rg + 16 * j;
            int gn = base + row;
            const float* xo = insh + row * UP;
            float h0 = fmaxf(unpk_sum(acc[j][0]), 0.f) + xo[c2];
            float h1 = fmaxf(unpk_sum(acc[j][1]), 0.f) + xo[c2 + 1];
            float h2 = fmaxf(unpk_sum(acc[j][2]), 0.f) + xo[32 + c2];
            float h3 = fmaxf(unpk_sum(acc[j][3]), 0.f) + xo[33 + c2];
            float s1 = h0 + h1 + h2 + h3;
            float s2 = h0 * h0 + h1 * h1 + h2 * h2 + h3 * h3;
            #pragma unroll
            for (int d = 1; d < 16; d <<= 1) {
                s1 += __shfl_xor_sync(0xFFFFFFFFu, s1, d);
                s2 += __shfl_xor_sync(0xFFFFFFFFu, s2, d);
            }
            float mu  = s1 * 0.015625f;
            float var = s2 * 0.015625f - mu * mu;
            float sc  = rsqrtf(fmaxf(var, 0.f) + 1e-5f);
            if (gn < NN) {
                float o0 = (h0 - mu) * sc * gsh[c2]      + b2sh[c2];
                float o1 = (h1 - mu) * sc * gsh[c2 + 1]  + b2sh[c2 + 1];
                float o2 = (h2 - mu) * sc * gsh[32 + c2] + b2sh[32 + c2];
                float o3 = (h3 - mu) * sc * gsh[33 + c2] + b2sh[33 + c2];
                *(float2*)(g_x + (size_t)gn * H + c2)      = make_float2(o0, o1);
                *(float2*)(g_x + (size_t)gn * H + 32 + c2) = make_float2(o2, o3);
            }
        }
        __syncthreads();
    }
}

// ---------- final mean/max over nodes ----------
__global__ void k_reduce() {
    __shared__ float rs[4][64];
    __shared__ float rm[4][64];
    int j = threadIdx.x & 63, g = threadIdx.x >> 6;
    float s = 0.f, m = -3.402823466e38f;
    for (int n = blockIdx.x * 4 + g; n < NN; n += gridDim.x * 4) {
        float v = g_x[(size_t)n * H + j];
        s += v; m = fmaxf(m, v);
    }
    rs[g][j] = s; rm[g][j] = m;
    __syncthreads();
    if (g == 0) {
        #pragma unroll
        for (int i = 1; i < 4; i++) { s += rs[i][j]; m = fmaxf(m, rm[i][j]); }
        atomicAdd(&g_sum[j], s);
        atomicMax(&g_maxb[j], encf(m));
    }
}

__global__ void k_final(float* out) {
    int t = threadIdx.x;
    if (t < 64) out[t] = g_sum[t] * (1.0f / NN);
    else        out[t] = decf(g_maxb[t - 64]);
}

// ---------- launch ----------
extern "C" void kernel_launch(void* const* d_in, const int* in_sizes, int n_in,
                              void* d_out, int out_size) {
    const int*   ti    = (const int*)d_in[0];
    const int*   edges = (const int*)d_in[1];
    const float* et    = (const float*)d_in[2];
    const float* msg_w = (const float*)d_in[3];
    const float* msg_b = (const float*)d_in[4];
    const float* upd_w = (const float*)d_in[5];
    const float* upd_b = (const float*)d_in[6];
    const float* lng   = (const float*)d_in[7];
    const float* lnb   = (const float*)d_in[8];
    float* out = (float*)d_out;

    cudaFuncSetAttribute(k_proj, cudaFuncAttributeMaxDynamicSharedMemorySize, SMEM_PROJ);
    cudaFuncSetAttribute(k_upd,  cudaFuncAttributeMaxDynamicSharedMemorySize, SMEM_UPD);

    k_embed<<<512, 256>>>(ti, et);
    k_hist<<<512, 256>>>(edges);
    k_prepack<<<96, 256>>>(msg_w, upd_w);

    // layer-0 proj placed 4th so ncu (-s5 -c1) profiles it
    static float* wpp_base = nullptr;
    static float* wpu_base = nullptr;
    if (!wpp_base) {
        cudaGetSymbolAddress((void**)&wpp_base, g_wpp);
        cudaGetSymbolAddress((void**)&wpu_base, g_wpu);
    }
    k_proj<<<296, NT, SMEM_PROJ>>>(wpp_base, msg_b);

    k_scan1<<<NBLK, 256>>>();
    k_scan2<<<1, 512>>>();
    k_scan3<<<392, 256>>>();
    k_scatter<<<(NE + 255) / 256, 256>>>(edges);

    for (int l = 0; l < 3; l++) {
        if (l > 0) k_proj<<<296, NT, SMEM_PROJ>>>(wpp_base + l * 8192, msg_b + l * 64);
        k_edge<<<NN * 8 / NT, NT>>>();
        k_upd<<<444, NT, SMEM_UPD>>>(wpu_base + l * 8192, upd_b + l * 64,
                                     lng + l * 64, lnb + l * 64);
    }

    k_reduce<<<296, 256>>>();
    k_final<<<1, 128>>>(out);
}

// round 6
// speedup vs baseline: 1.5868x; 1.0280x over previous
#include <cuda_runtime.h>
#include <cstdint>

#define NN 100000
#define NE 800000
#define H  64
#define NT 256
#define XP 68                  // proj x smem pitch (floats)
#define UP 132                 // upd in smem pitch (floats)
#define SMEM_PROJ ((8192 + 2 * 64 * XP) * 4)
#define SMEM_UPD  ((8192 + 192 + 2 * 64 * UP) * 4)
#define NBLK 391               // scan blocks (391*256 >= NN)

// Scratch (device globals: allocation-free rule)
__device__ __align__(16) float g_x[(size_t)NN * H];
__device__ __align__(16) float g_p1[(size_t)NN * H];
__device__ __align__(16) float g_p2[(size_t)NN * H];
__device__ __align__(16) float g_agg[(size_t)NN * H];
__device__ __align__(16) float g_wpp[3 * 8192];   // proj weights, pair-packed
__device__ __align__(16) float g_wpu[3 * 8192];   // upd weights, pair-packed
__device__ int g_deg[NN];
__device__ int g_off[NN + 1];
__device__ int g_cur[NN];
__device__ int g_csr[NE];
__device__ int g_bsum[NBLK];
__device__ int g_boff[NBLK];
__device__ float g_sum[H];
__device__ unsigned g_maxb[H];

// ---------- packed f32x2 + async-copy helpers ----------
__device__ __forceinline__ uint64_t pk2(float lo, float hi) {
    uint64_t r;
    asm("mov.b64 %0, {%1, %2};" : "=l"(r) : "r"(__float_as_uint(lo)), "r"(__float_as_uint(hi)));
    return r;
}
__device__ __forceinline__ void fma2(uint64_t& acc, uint64_t w, uint64_t p) {
    asm("fma.rn.f32x2 %0, %1, %2, %0;" : "+l"(acc) : "l"(w), "l"(p));
}
__device__ __forceinline__ float unpk_sum(uint64_t v) {
    unsigned a, b;
    asm("mov.b64 {%0, %1}, %2;" : "=r"(a), "=r"(b) : "l"(v));
    return __uint_as_float(a) + __uint_as_float(b);
}
__device__ __forceinline__ void cpa16(float* dst_smem, const float* src) {
    unsigned d = (unsigned)__cvta_generic_to_shared(dst_smem);
    asm volatile("cp.async.cg.shared.global [%0], [%1], 16;" :: "r"(d), "l"(src));
}
__device__ __forceinline__ void cpa_commit() {
    asm volatile("cp.async.commit_group;");
}
__device__ __forceinline__ void cpa_wait1() {
    asm volatile("cp.async.wait_group 1;");
}
__device__ __forceinline__ unsigned encf(float f) {
    unsigned u = __float_as_uint(f);
    return (u & 0x80000000u) ? ~u : (u | 0x80000000u);
}
__device__ __forceinline__ float decf(unsigned u) {
    return (u & 0x80000000u) ? __uint_as_float(u & 0x7FFFFFFFu) : __uint_as_float(~u);
}

// ---------- setup ----------
__global__ void k_embed(const int* __restrict__ ti, const float* __restrict__ et) {
    int i = blockIdx.x * blockDim.x + threadIdx.x;
    int stride = gridDim.x * blockDim.x;
    for (int lin = i; lin < NN * 16; lin += stride) {
        int n = lin >> 4, q = lin & 15;
        ((float4*)g_x)[lin] = ((const float4*)et)[ti[n] * 16 + q];
    }
    for (int n = i; n < NN; n += stride) g_deg[n] = 0;
    if (i < H) { g_sum[i] = 0.f; g_maxb[i] = 0u; }
}

__global__ void k_hist(const int* __restrict__ edges) {
    int i = blockIdx.x * blockDim.x + threadIdx.x;
    int stride = gridDim.x * blockDim.x;
    for (int e = i; e < NE; e += stride)
        atomicAdd(&g_deg[((const int2*)edges)[e].y], 1);
}

// ---------- weight prepack: pair-major (k-pair packed) layouts ----------
__global__ void k_prepack(const float* __restrict__ msg_w, const float* __restrict__ upd_w) {
    int i = blockIdx.x * blockDim.x + threadIdx.x;
    int stride = gridDim.x * blockDim.x;
    for (int idx = i; idx < 3 * 8192; idx += stride) {
        int l = idx / 8192, r = idx % 8192;
        int s = r & 1, tC = r >> 1;
        int C = tC & 127, t = tC >> 7;
        int row = (C < 64) ? (2 * t + s) : (64 + 2 * t + s);
        g_wpp[idx] = msg_w[l * 8192 + row * 64 + (C & 63)];
    }
    for (int idx = i; idx < 3 * 8192; idx += stride) {
        int l = idx / 8192, r = idx % 8192;
        int s = r & 1, tc = r >> 1;
        int c = tc & 63, t = tc >> 6;
        g_wpu[idx] = upd_w[l * 8192 + (2 * t + s) * 64 + c];
    }
}

// ---------- exclusive scan of g_deg -> g_off ----------
__global__ void k_scan1() {
    __shared__ int s[256];
    int t = threadIdx.x;
    int i = blockIdx.x * 256 + t;
    int v = (i < NN) ? g_deg[i] : 0;
    s[t] = v;
    __syncthreads();
    #pragma unroll
    for (int d = 1; d < 256; d <<= 1) {
        int tv = (t >= d) ? s[t - d] : 0;
        __syncthreads();
        s[t] += tv;
        __syncthreads();
    }
    if (i < NN) g_off[i] = s[t] - v;
    if (t == 255) g_bsum[blockIdx.x] = s[255];
}

__global__ void k_scan2() {
    __shared__ int s[512];
    int t = threadIdx.x;
    int v = (t < NBLK) ? g_bsum[t] : 0;
    s[t] = v;
    __syncthreads();
    #pragma unroll
    for (int d = 1; d < 512; d <<= 1) {
        int tv = (t >= d) ? s[t - d] : 0;
        __syncthreads();
        s[t] += tv;
        __syncthreads();
    }
    if (t < NBLK) g_boff[t] = s[t] - v;
}

__global__ void k_scan3() {
    int i = blockIdx.x * blockDim.x + threadIdx.x;
    if (i < NN) {
        int val = g_off[i] + g_boff[i >> 8];
        g_off[i] = val;
        g_cur[i] = val;
    }
    if (i == 0) g_off[NN] = NE;
}

__global__ void k_scatter(const int* __restrict__ edges) {
    int e = blockIdx.x * blockDim.x + threadIdx.x;
    if (e < NE) {
        int2 ed = ((const int2*)edges)[e];
        int pos = atomicAdd(&g_cur[ed.y], 1);
        g_csr[pos] = ed.x;
    }
}

// ---------- per-node projection: P1 = x@W[:64]; P2 = x@W[64:] + b ----------
// k-pair packed, cp.async double-buffered. thread: 8 rows x (2 P1 + 2 P2 cols).
__global__ __launch_bounds__(NT, 2) void k_proj(const float* __restrict__ Wp,
                                                const float* __restrict__ B) {
    extern __shared__ float sm[];
    float* Wsh = sm;                    // 8192 pair-packed
    float* xbuf[2] = { sm + 8192, sm + 8192 + 64 * XP };

    const int tid = threadIdx.x;
    for (int i = tid; i < 2048; i += NT) ((float4*)Wsh)[i] = ((const float4*)Wp)[i];

    const int cg = tid & 31, rg = tid >> 5;
    const int c2 = cg * 2;
    const float bias0 = B[c2], bias1 = B[c2 + 1];

    const int l_nl = tid >> 4, l_q = tid & 15;   // load map: 4 rows-chunks per thread
    const int ntiles = (NN + 63) / 64;

    // prologue: load first tile into buf 0
    {
        int base = blockIdx.x * 64;
        #pragma unroll
        for (int r = 0; r < 4; r++) {
            int nl = l_nl + r * 16;
            int gn = base + nl; if (gn >= NN) gn = NN - 1;
            cpa16(xbuf[0] + nl * XP + l_q * 4, g_x + (size_t)gn * H + l_q * 4);
        }
    }
    cpa_commit();

    int sel = 0;
    for (int tile = blockIdx.x; tile < ntiles; tile += gridDim.x) {
        int nxt = tile + gridDim.x;
        if (nxt < ntiles) {
            int base = nxt * 64;
            #pragma unroll
            for (int r = 0; r < 4; r++) {
                int nl = l_nl + r * 16;
                int gn = base + nl; if (gn >= NN) gn = NN - 1;
                cpa16(xbuf[sel ^ 1] + nl * XP + l_q * 4, g_x + (size_t)gn * H + l_q * 4);
            }
        }
        cpa_commit();
        cpa_wait1();
        __syncthreads();

        const float* xb = xbuf[sel];
        const int base = tile * 64;

        uint64_t acc[8][4];
        {
            uint64_t zb0 = pk2(bias0, 0.f), zb1 = pk2(bias1, 0.f);
            #pragma unroll
            for (int j = 0; j < 8; j++) {
                acc[j][0] = 0;   acc[j][1] = 0;
                acc[j][2] = zb0; acc[j][3] = zb1;
            }
        }

        #pragma unroll 2
        for (int t2 = 0; t2 < 16; t2++) {
            ulonglong2 xv[8];
            #pragma unroll
            for (int j = 0; j < 8; j++)
                xv[j] = *(const ulonglong2*)(xb + (rg + 8 * j) * XP + 4 * t2);
            #pragma unroll
            for (int p = 0; p < 2; p++) {
                int t = 2 * t2 + p;
                ulonglong2 w1 = *(const ulonglong2*)(Wsh + (t * 128 + c2) * 2);
                ulonglong2 w2 = *(const ulonglong2*)(Wsh + (t * 128 + 64 + c2) * 2);
                #pragma unroll
                for (int j = 0; j < 8; j++) {
                    uint64_t x2 = p ? xv[j].y : xv[j].x;
                    fma2(acc[j][0], w1.x, x2); fma2(acc[j][1], w1.y, x2);
                    fma2(acc[j][2], w2.x, x2); fma2(acc[j][3], w2.y, x2);
                }
            }
        }

        #pragma unroll
        for (int j = 0; j < 8; j++) {
            int gn = base + rg + 8 * j;
            if (gn < NN) {
                *(float2*)(g_p1 + (size_t)gn * H + c2) =
                    make_float2(unpk_sum(acc[j][0]), unpk_sum(acc[j][1]));
                *(float2*)(g_p2 + (size_t)gn * H + c2) =
                    make_float2(unpk_sum(acc[j][2]), unpk_sum(acc[j][3]));
            }
        }
        __syncthreads();   // all reads of xbuf[sel] done before it is reloaded
        sel ^= 1;
    }
}

// ---------- CSR edge pass: agg[n] = mean-ready sum of relu(P1[src] + P2[n]) ----------
__global__ __launch_bounds__(NT) void k_edge() {
    int idx = blockIdx.x * NT + threadIdx.x;  // NN*8 tasks exactly
    int n = idx >> 3, q = idx & 7;
    int s0 = g_off[n], s1 = g_off[n + 1];
    const float4* p2 = (const float4*)(g_p2 + (size_t)n * H) + q * 2;
    float4 b0 = p2[0], b1 = p2[1];
    float a[8] = {0.f, 0.f, 0.f, 0.f, 0.f, 0.f, 0.f, 0.f};
    for (int i = s0; i < s1; i++) {
        int src = g_csr[i];
        const float4* p1 = (const float4*)(g_p1 + (size_t)src * H) + q * 2;
        float4 c0 = p1[0], c1 = p1[1];
        a[0] += fmaxf(c0.x + b0.x, 0.f); a[1] += fmaxf(c0.y + b0.y, 0.f);
        a[2] += fmaxf(c0.z + b0.z, 0.f); a[3] += fmaxf(c0.w + b0.w, 0.f);
        a[4] += fmaxf(c1.x + b1.x, 0.f); a[5] += fmaxf(c1.y + b1.y, 0.f);
        a[6] += fmaxf(c1.z + b1.z, 0.f); a[7] += fmaxf(c1.w + b1.w, 0.f);
    }
    float ic = 1.0f / fmaxf((float)(s1 - s0), 1.0f);   // fold mean into agg
    float4* dst = (float4*)(g_agg + (size_t)n * H + q * 8);
    dst[0] = make_float4(a[0] * ic, a[1] * ic, a[2] * ic, a[3] * ic);
    dst[1] = make_float4(a[4] * ic, a[5] * ic, a[6] * ic, a[7] * ic);
}

// ---------- node update GEMM + residual + LayerNorm ----------
// k-pair packed, cp.async double-buffered. thread: 4 rows x 4 cols.
__global__ __launch_bounds__(NT, 2) void k_upd(const float* __restrict__ Wp,
                                               const float* __restrict__ B,
                                               const float* __restrict__ lng,
                                               const float* __restrict__ lnb) {
    extern __shared__ float sm[];
    float* Wsh  = sm;            // 8192 pair-packed
    float* bsh  = sm + 8192;     // 64
    float* gsh  = sm + 8256;     // 64
    float* b2sh = sm + 8320;     // 64
    float* ibuf[2] = { sm + 8384, sm + 8384 + 64 * UP };

    const int tid = threadIdx.x;
    for (int i = tid; i < 2048; i += NT) ((float4*)Wsh)[i] = ((const float4*)Wp)[i];
    if (tid < 16) ((float4*)bsh)[tid] = ((const float4*)B)[tid];
    else if (tid < 32) ((float4*)gsh)[tid - 16]  = ((const float4*)lng)[tid - 16];
    else if (tid < 48) ((float4*)b2sh)[tid - 32] = ((const float4*)lnb)[tid - 32];

    const int cg = tid & 15, rg = tid >> 4;
    const int c2 = cg * 2;

    const int l_nl = tid >> 5, l_q = tid & 31;  // load map: 8 row-chunks per thread
    const int ntiles = (NN + 63) / 64;

    {
        int base = blockIdx.x * 64;
        #pragma unroll
        for (int r = 0; r < 8; r++) {
            int nl = l_nl + r * 8;
            int gn = base + nl; if (gn >= NN) gn = NN - 1;
            const float* src = (l_q < 16) ? (g_x + (size_t)gn * H + l_q * 4)
                                          : (g_agg + (size_t)gn * H + (l_q - 16) * 4);
            cpa16(ibuf[0] + nl * UP + l_q * 4, src);
        }
    }
    cpa_commit();

    int sel = 0;
    for (int tile = blockIdx.x; tile < ntiles; tile += gridDim.x) {
        int nxt = tile + gridDim.x;
        if (nxt < ntiles) {
            int base = nxt * 64;
            #pragma unroll
            for (int r = 0; r < 8; r++) {
                int nl = l_nl + r * 8;
                int gn = base + nl; if (gn >= NN) gn = NN - 1;
                const float* src = (l_q < 16) ? (g_x + (size_t)gn * H + l_q * 4)
                                              : (g_agg + (size_t)gn * H + (l_q - 16) * 4);
                cpa16(ibuf[sel ^ 1] + nl * UP + l_q * 4, src);
            }
        }
        cpa_commit();
        cpa_wait1();
        __syncthreads();

        const float* xb = ibuf[sel];
        const int base = tile * 64;

        uint64_t acc[4][4];
        {
            uint64_t b0 = pk2(bsh[c2], 0.f),      b1 = pk2(bsh[c2 + 1], 0.f);
            uint64_t b2 = pk2(bsh[32 + c2], 0.f), b3 = pk2(bsh[33 + c2], 0.f);
            #pragma unroll
            for (int j = 0; j < 4; j++) {
                acc[j][0] = b0; acc[j][1] = b1; acc[j][2] = b2; acc[j][3] = b3;
            }
        }

        #pragma unroll 4
        for (int t2 = 0; t2 < 32; t2++) {
            ulonglong2 xv[4];
            #pragma unroll
            for (int j = 0; j < 4; j++)
                xv[j] = *(const ulonglong2*)(xb + (rg + 16 * j) * UP + 4 * t2);
            #pragma unroll
            for (int p = 0; p < 2; p++) {
                int t = 2 * t2 + p;
                ulonglong2 w1 = *(const ulonglong2*)(Wsh + (t * 64 + c2) * 2);
                ulonglong2 w2 = *(const ulonglong2*)(Wsh + (t * 64 + 32 + c2) * 2);
                #pragma unroll
                for (int j = 0; j < 4; j++) {
                    uint64_t x2 = p ? xv[j].y : xv[j].x;
                    fma2(acc[j][0], w1.x, x2); fma2(acc[j][1], w1.y, x2);
                    fma2(acc[j][2], w2.x, x2); fma2(acc[j][3], w2.y, x2);
                }
            }
        }

        #pragma unroll
        for (int j = 0; j < 4; j++) {
            int row = rg + 16 * j;
            int gn = base + row;
            const float* xo = xb + row * UP;
            float h0 = fmaxf(unpk_sum(acc[j][0]), 0.f) + xo[c2];
            float h1 = fmaxf(unpk_sum(acc[j][1]), 0.f) + xo[c2 + 1];
            float h2 = fmaxf(unpk_sum(acc[j][2]), 0.f) + xo[32 + c2];
            float h3 = fmaxf(unpk_sum(acc[j][3]), 0.f) + xo[33 + c2];
            float s1 = h0 + h1 + h2 + h3;
            float s2 = h0 * h0 + h1 * h1 + h2 * h2 + h3 * h3;
            #pragma unroll
            for (int d = 1; d < 16; d <<= 1) {
                s1 += __shfl_xor_sync(0xFFFFFFFFu, s1, d);
                s2 += __shfl_xor_sync(0xFFFFFFFFu, s2, d);
            }
            float mu  = s1 * 0.015625f;
            float var = s2 * 0.015625f - mu * mu;
            float sc  = rsqrtf(fmaxf(var, 0.f) + 1e-5f);
            if (gn < NN) {
                float o0 = (h0 - mu) * sc * gsh[c2]      + b2sh[c2];
                float o1 = (h1 - mu) * sc * gsh[c2 + 1]  + b2sh[c2 + 1];
                float o2 = (h2 - mu) * sc * gsh[32 + c2] + b2sh[32 + c2];
                float o3 = (h3 - mu) * sc * gsh[33 + c2] + b2sh[33 + c2];
                *(float2*)(g_x + (size_t)gn * H + c2)      = make_float2(o0, o1);
                *(float2*)(g_x + (size_t)gn * H + 32 + c2) = make_float2(o2, o3);
            }
        }
        __syncthreads();
        sel ^= 1;
    }
}

// ---------- final mean/max over nodes ----------
__global__ void k_reduce() {
    __shared__ float rs[4][64];
    __shared__ float rm[4][64];
    int j = threadIdx.x & 63, g = threadIdx.x >> 6;
    float s = 0.f, m = -3.402823466e38f;
    for (int n = blockIdx.x * 4 + g; n < NN; n += gridDim.x * 4) {
        float v = g_x[(size_t)n * H + j];
        s += v; m = fmaxf(m, v);
    }
    rs[g][j] = s; rm[g][j] = m;
    __syncthreads();
    if (g == 0) {
        #pragma unroll
        for (int i = 1; i < 4; i++) { s += rs[i][j]; m = fmaxf(m, rm[i][j]); }
        atomicAdd(&g_sum[j], s);
        atomicMax(&g_maxb[j], encf(m));
    }
}

__global__ void k_final(float* out) {
    int t = threadIdx.x;
    if (t < 64) out[t] = g_sum[t] * (1.0f / NN);
    else        out[t] = decf(g_maxb[t - 64]);
}

// ---------- launch ----------
extern "C" void kernel_launch(void* const* d_in, const int* in_sizes, int n_in,
                              void* d_out, int out_size) {
    const int*   ti    = (const int*)d_in[0];
    const int*   edges = (const int*)d_in[1];
    const float* et    = (const float*)d_in[2];
    const float* msg_w = (const float*)d_in[3];
    const float* msg_b = (const float*)d_in[4];
    const float* upd_w = (const float*)d_in[5];
    const float* upd_b = (const float*)d_in[6];
    const float* lng   = (const float*)d_in[7];
    const float* lnb   = (const float*)d_in[8];
    float* out = (float*)d_out;

    cudaFuncSetAttribute(k_proj, cudaFuncAttributeMaxDynamicSharedMemorySize, SMEM_PROJ);
    cudaFuncSetAttribute(k_upd,  cudaFuncAttributeMaxDynamicSharedMemorySize, SMEM_UPD);

    k_embed<<<512, 256>>>(ti, et);
    k_hist<<<512, 256>>>(edges);
    k_prepack<<<96, 256>>>(msg_w, upd_w);

    static float* wpp_base = nullptr;
    static float* wpu_base = nullptr;
    if (!wpp_base) {
        cudaGetSymbolAddress((void**)&wpp_base, g_wpp);
        cudaGetSymbolAddress((void**)&wpu_base, g_wpu);
    }
    // layer-0 proj placed 4th so ncu (-s5 -c1) profiles it
    k_proj<<<296, NT, SMEM_PROJ>>>(wpp_base, msg_b);

    k_scan1<<<NBLK, 256>>>();
    k_scan2<<<1, 512>>>();
    k_scan3<<<392, 256>>>();
    k_scatter<<<(NE + 255) / 256, 256>>>(edges);

    for (int l = 0; l < 3; l++) {
        if (l > 0) k_proj<<<296, NT, SMEM_PROJ>>>(wpp_base + l * 8192, msg_b + l * 64);
        k_edge<<<NN * 8 / NT, NT>>>();
        k_upd<<<296, NT, SMEM_UPD>>>(wpu_base + l * 8192, upd_b + l * 64,
                                     lng + l * 64, lnb + l * 64);
    }

    k_reduce<<<296, 256>>>();
    k_final<<<1, 128>>>(out);
}